// round 15
// baseline (speedup 1.0000x reference)
#include <cuda_runtime.h>
#include <cuda_fp16.h>
#include <mma.h>
#include <math.h>
#include <stdint.h>

using namespace nvcuda;

#define T_TOK 16384
#define DDIM  512
#define HDIM  2048
#define NEXP  16
#define TOPK  4

#define BM    128
#define BN    256
#define BK    64
#define SA    72            // smem row stride (halves), 144B rows
#define CLD   260           // gemm1 epilogue float stage stride
#define SLOTS (T_TOK * TOPK + NEXP * BM)   // per-expert regions padded to BM

#define STAGE_HALVES ((BM + BN) * SA)              // 27648 halves = 55296 B
#define DSM_BYTES    (BM * CLD * 4)                // 133120 > 2 stages (110592)

// ---------------------------------------------------------------------------
// device scratch (allocation-free)
// ---------------------------------------------------------------------------
__device__ int    g_count[NEXP];
__device__ int    g_tok [NEXP * T_TOK];
__device__ float  g_gate[NEXP * T_TOK];
__device__ int    g_inv [T_TOK * TOPK];                 // e*T_TOK + pos
__device__ __half d_xh  [(size_t)T_TOK * DDIM];
__device__ __half d_w1t [(size_t)NEXP * HDIM * DDIM];   // [e][n(H)][k(D)]
__device__ __half d_w2t [(size_t)NEXP * DDIM * HDIM];   // [e][n(D)][k(H)]
__device__ __half d_hbuf[(size_t)SLOTS * HDIM];         // fp16 hidden acts
__device__ float  d_ybuf[(size_t)SLOTS * DDIM];         // fp32 expert outputs

// BM-padded prefix offset of expert e (replaces scan_kernel)
__device__ __forceinline__ int expert_off(int e) {
    int s = 0;
#pragma unroll
    for (int i = 0; i < NEXP; i++)
        if (i < e) s += ((g_count[i] + BM - 1) / BM) * BM;
    return s;
}

// ---------------------------------------------------------------------------
// helpers
// ---------------------------------------------------------------------------
__device__ __forceinline__ uint32_t smem_u32(const void* p) {
    uint32_t a;
    asm("{ .reg .u64 t; cvta.to.shared.u64 t, %1; cvt.u32.u64 %0, t; }"
        : "=r"(a) : "l"(p));
    return a;
}
#define CP_ASYNC16(dst, src, sz) \
    asm volatile("cp.async.cg.shared.global [%0], [%1], 16, %2;" \
                 :: "r"(dst), "l"(src), "r"(sz) : "memory")
#define CP_COMMIT() asm volatile("cp.async.commit_group;" ::: "memory")
#define CP_WAIT1()  asm volatile("cp.async.wait_group 1;" ::: "memory")
#define CP_WAIT0()  asm volatile("cp.async.wait_group 0;" ::: "memory")

// ---------------------------------------------------------------------------
// K1: convert x -> fp16 (+ reset expert counts)
// ---------------------------------------------------------------------------
__global__ void convx_kernel(const float4* __restrict__ x, int n4) {
    int i = blockIdx.x * blockDim.x + threadIdx.x;
    if (blockIdx.x == 0 && threadIdx.x < NEXP) g_count[threadIdx.x] = 0;
    if (i >= n4) return;
    float4 v = x[i];
    __half2 a = __floats2half2_rn(v.x, v.y);
    __half2 b = __floats2half2_rn(v.z, v.w);
    ((uint2*)d_xh)[i] = make_uint2(*(uint32_t*)&a, *(uint32_t*)&b);
}

// ---------------------------------------------------------------------------
// K2: transpose+convert BOTH weights in one launch
// (dst selected in device code — host-side __device__ symbol = ATS bug)
// ---------------------------------------------------------------------------
__global__ __launch_bounds__(256)
void trans_kernel(const float* __restrict__ w1, const float* __restrict__ w2) {
    __shared__ float t[32][33];
    int which = blockIdx.z;
    int R = which ? HDIM : DDIM;
    int C = which ? DDIM : HDIM;
    const float* srcbase = which ? w2 : w1;
    __half* dstbase = which ? d_w2t : d_w1t;
    int e = blockIdx.y;
    int rt_ = which ? (blockIdx.x & 63) : (blockIdx.x & 15);
    int ct_ = which ? (blockIdx.x >> 6) : (blockIdx.x >> 4);
    int r0 = rt_ * 32, c0 = ct_ * 32;
    const float* s = srcbase + (size_t)e * R * C;
    __half* d = dstbase + (size_t)e * R * C;
    int tx = threadIdx.x & 31, ty = threadIdx.x >> 5;
#pragma unroll
    for (int p = 0; p < 4; p++)
        t[ty + p * 8][tx] = s[(size_t)(r0 + ty + p * 8) * C + c0 + tx];
    __syncthreads();
#pragma unroll
    for (int p = 0; p < 4; p++)
        d[(size_t)(c0 + ty + p * 8) * R + r0 + tx] =
            __float2half_rn(t[tx][ty + p * 8]);
}

// ---------------------------------------------------------------------------
// K3: router (+ inverse map for combine)
// ---------------------------------------------------------------------------
__global__ __launch_bounds__(256)
void router_kernel(const float* __restrict__ x,
                   const float* __restrict__ rw,
                   const float* __restrict__ rb) {
    __shared__ float s_rw[DDIM * NEXP];
    __shared__ float s_rb[NEXP];
    for (int i = threadIdx.x; i < DDIM * NEXP; i += 256) s_rw[i] = rw[i];
    if (threadIdx.x < NEXP) s_rb[threadIdx.x] = rb[threadIdx.x];
    __syncthreads();

    int warp = threadIdx.x >> 5, lane = threadIdx.x & 31;
    int t0 = (blockIdx.x * 8 + warp) * 4;
    if (t0 >= T_TOK) return;

    float acc[4][NEXP];
#pragma unroll
    for (int tt = 0; tt < 4; tt++)
#pragma unroll
        for (int e = 0; e < NEXP; e++) acc[tt][e] = 0.f;

#pragma unroll 4
    for (int di = 0; di < 16; di++) {
        int d = di * 32 + lane;
        float xv[4];
#pragma unroll
        for (int tt = 0; tt < 4; tt++) xv[tt] = x[(size_t)(t0 + tt) * DDIM + d];
#pragma unroll
        for (int e = 0; e < NEXP; e++) {
            float w = s_rw[d * NEXP + e];
#pragma unroll
            for (int tt = 0; tt < 4; tt++) acc[tt][e] = fmaf(xv[tt], w, acc[tt][e]);
        }
    }
#pragma unroll
    for (int tt = 0; tt < 4; tt++)
#pragma unroll
        for (int e = 0; e < NEXP; e++) {
            float v = acc[tt][e];
#pragma unroll
            for (int off = 16; off > 0; off >>= 1)
                v += __shfl_xor_sync(0xffffffffu, v, off);
            acc[tt][e] = v;
        }
    if (lane == 0) {
#pragma unroll
        for (int tt = 0; tt < 4; tt++) {
            int t = t0 + tt;
            float v[NEXP];
#pragma unroll
            for (int e = 0; e < NEXP; e++) v[e] = acc[tt][e] + s_rb[e];
            float sv[TOPK]; int si[TOPK];
#pragma unroll
            for (int k = 0; k < TOPK; k++) {
                float bm = -1e30f; int bi = 0;
#pragma unroll
                for (int e = 0; e < NEXP; e++)
                    if (v[e] > bm) { bm = v[e]; bi = e; }
                sv[k] = bm; si[k] = bi; v[bi] = -1e30f;
            }
            float mx = sv[0], s = 0.f, g[TOPK];
#pragma unroll
            for (int k = 0; k < TOPK; k++) { g[k] = __expf(sv[k] - mx); s += g[k]; }
            float inv = 1.f / s;
#pragma unroll
            for (int k = 0; k < TOPK; k++) {
                int e = si[k];
                int pos = atomicAdd(&g_count[e], 1);
                g_tok [e * T_TOK + pos] = t;
                g_gate[e * T_TOK + pos] = g[k] * inv;
                g_inv [t * TOPK + k]    = e * T_TOK + pos;
            }
        }
    }
}

// ---------------------------------------------------------------------------
// shared wmma compute: 8 warps (2m x 4n), warp tile 64x64, block 128x256
// 2 warps per SMSP in one CTA -> latency interleaving the R12 config lacked
// ---------------------------------------------------------------------------
__device__ __forceinline__ void wmma_stage(
    const __half* As, const __half* Bs, int wm, int wn,
    wmma::fragment<wmma::accumulator, 16, 16, 16, float> (&acc)[4][4]) {
#pragma unroll
    for (int ks = 0; ks < BK / 16; ks++) {
        wmma::fragment<wmma::matrix_a, 16, 16, 16, __half, wmma::row_major> af[4];
#pragma unroll
        for (int mt = 0; mt < 4; mt++)
            wmma::load_matrix_sync(af[mt],
                &As[(wm * 64 + mt * 16) * SA + ks * 16], SA);
#pragma unroll
        for (int nt = 0; nt < 4; nt++) {
            wmma::fragment<wmma::matrix_b, 16, 16, 16, __half, wmma::col_major> bf;
            wmma::load_matrix_sync(bf,
                &Bs[(wn * 64 + nt * 16) * SA + ks * 16], SA);
#pragma unroll
            for (int mt = 0; mt < 4; mt++)
                wmma::mma_sync(acc[mt][nt], af[mt], bf, acc[mt][nt]);
        }
    }
}

// ---------------------------------------------------------------------------
// K4: GEMM1  H[slot] = relu(gather(X) @ W1^T + b1)   M=128 N=256 K=512
// ---------------------------------------------------------------------------
__global__ __launch_bounds__(256, 1)
void gemm1_kernel(const float* __restrict__ b1) {
    int e = blockIdx.z;
    int cnt = g_count[e];
    int m0 = blockIdx.y * BM;
    if (m0 >= cnt) return;
    int nrows = min(BM, cnt - m0);
    int n0 = blockIdx.x * BN;
    int off_e = expert_off(e);

    extern __shared__ __align__(16) char dsm[];
    __half* stage[2] = {(__half*)dsm, (__half*)dsm + STAGE_HALVES};
    float*  Cs = (float*)dsm;
    __shared__ int s_tok[BM];

    int tid = threadIdx.x, wid = tid >> 5;
    int wm = wid & 1, wn = wid >> 1;

    if (tid < BM) s_tok[tid] = (tid < nrows) ? g_tok[e * T_TOK + m0 + tid] : -1;
    __syncthreads();

    const __half* bsrc = d_w1t + ((size_t)e * HDIM + n0) * DDIM;
    const int NC = DDIM / BK;   // 8

#define G1_LOAD(c, buf) do {                                                    \
    int kc = (c) * BK;                                                          \
    __half* As_ = stage[buf];                                                   \
    __half* Bs_ = stage[buf] + BM * SA;                                         \
    _Pragma("unroll")                                                           \
    for (int it = 0; it < 4; it++) {                                            \
        int idx = it * 256 + tid;                                               \
        int r = idx >> 3, c8 = idx & 7;                                         \
        int tok = s_tok[r];                                                     \
        const __half* src = d_xh + (size_t)(tok < 0 ? 0 : tok) * DDIM + kc + c8 * 8; \
        CP_ASYNC16(smem_u32(&As_[r * SA + c8 * 8]), src, (tok >= 0) ? 16 : 0);  \
    }                                                                           \
    _Pragma("unroll")                                                           \
    for (int it = 0; it < 8; it++) {                                            \
        int idx = it * 256 + tid;                                               \
        int r = idx >> 3, c8 = idx & 7;                                         \
        CP_ASYNC16(smem_u32(&Bs_[r * SA + c8 * 8]),                             \
                   bsrc + (size_t)r * DDIM + kc + c8 * 8, 16);                  \
    }                                                                           \
    CP_COMMIT();                                                                \
} while (0)

    wmma::fragment<wmma::accumulator, 16, 16, 16, float> acc[4][4];
#pragma unroll
    for (int mt = 0; mt < 4; mt++)
#pragma unroll
        for (int nt = 0; nt < 4; nt++) wmma::fill_fragment(acc[mt][nt], 0.f);

    G1_LOAD(0, 0);
    G1_LOAD(1, 1);

    for (int c = 0; c < NC; c++) {
        if (c + 1 < NC) CP_WAIT1(); else CP_WAIT0();
        __syncthreads();
        int buf = c & 1;
        wmma_stage(stage[buf], stage[buf] + BM * SA, wm, wn, acc);
        __syncthreads();
        if (c + 2 < NC) G1_LOAD(c + 2, buf);
    }
#undef G1_LOAD

    __syncthreads();
#pragma unroll
    for (int mt = 0; mt < 4; mt++)
#pragma unroll
        for (int nt = 0; nt < 4; nt++)
            wmma::store_matrix_sync(
                &Cs[(wm * 64 + mt * 16) * CLD + wn * 64 + nt * 16],
                acc[mt][nt], CLD, wmma::mem_row_major);
    __syncthreads();

    // epilogue: +b1, relu, fp16 -> hbuf  (128 rows x 128 col-pairs)
#pragma unroll 4
    for (int i = 0; i < 64; i++) {
        int idx = i * 256 + tid;
        int r = idx >> 7, c2 = (idx & 127) * 2;
        if (r >= nrows) continue;
        float v0 = Cs[r * CLD + c2]     + b1[e * HDIM + n0 + c2];
        float v1 = Cs[r * CLD + c2 + 1] + b1[e * HDIM + n0 + c2 + 1];
        __half2 hh = __floats2half2_rn(fmaxf(v0, 0.f), fmaxf(v1, 0.f));
        *(uint32_t*)&d_hbuf[(size_t)(off_e + m0 + r) * HDIM + n0 + c2] =
            *(uint32_t*)&hh;
    }
}

// ---------------------------------------------------------------------------
// K5: GEMM2  ybuf[slot] = H @ W2^T   M=128 N=256 K=2048
// direct fp32 tile store into padded slot region
// ---------------------------------------------------------------------------
__global__ __launch_bounds__(256, 1)
void gemm2_kernel() {
    int e = blockIdx.z;
    int cnt = g_count[e];
    int m0 = blockIdx.y * BM;
    if (m0 >= cnt) return;
    int nrows = min(BM, cnt - m0);
    int n0 = blockIdx.x * BN;
    int off_e = expert_off(e);

    extern __shared__ __align__(16) char dsm[];
    __half* stage[2] = {(__half*)dsm, (__half*)dsm + STAGE_HALVES};

    int tid = threadIdx.x, wid = tid >> 5;
    int wm = wid & 1, wn = wid >> 1;

    const __half* asrc = d_hbuf + (size_t)(off_e + m0) * HDIM;
    const __half* bsrc = d_w2t + ((size_t)e * DDIM + n0) * HDIM;
    const int NC = HDIM / BK;   // 32

#define G2_LOAD(c, buf) do {                                                    \
    int kc = (c) * BK;                                                          \
    __half* As_ = stage[buf];                                                   \
    __half* Bs_ = stage[buf] + BM * SA;                                         \
    _Pragma("unroll")                                                           \
    for (int it = 0; it < 4; it++) {                                            \
        int idx = it * 256 + tid;                                               \
        int r = idx >> 3, c8 = idx & 7;                                         \
        int rs = (r < nrows) ? r : 0;                                           \
        CP_ASYNC16(smem_u32(&As_[r * SA + c8 * 8]),                             \
                   asrc + (size_t)rs * HDIM + kc + c8 * 8,                      \
                   (r < nrows) ? 16 : 0);                                       \
    }                                                                           \
    _Pragma("unroll")                                                           \
    for (int it = 0; it < 8; it++) {                                            \
        int idx = it * 256 + tid;                                               \
        int r = idx >> 3, c8 = idx & 7;                                         \
        CP_ASYNC16(smem_u32(&Bs_[r * SA + c8 * 8]),                             \
                   bsrc + (size_t)r * HDIM + kc + c8 * 8, 16);                  \
    }                                                                           \
    CP_COMMIT();                                                                \
} while (0)

    wmma::fragment<wmma::accumulator, 16, 16, 16, float> acc[4][4];
#pragma unroll
    for (int mt = 0; mt < 4; mt++)
#pragma unroll
        for (int nt = 0; nt < 4; nt++) wmma::fill_fragment(acc[mt][nt], 0.f);

    G2_LOAD(0, 0);
    G2_LOAD(1, 1);

    for (int c = 0; c < NC; c++) {
        if (c + 1 < NC) CP_WAIT1(); else CP_WAIT0();
        __syncthreads();
        int buf = c & 1;
        wmma_stage(stage[buf], stage[buf] + BM * SA, wm, wn, acc);
        __syncthreads();
        if (c + 2 < NC) G2_LOAD(c + 2, buf);
    }
#undef G2_LOAD

    float* ybase = d_ybuf + (size_t)(off_e + m0) * DDIM + n0;
#pragma unroll
    for (int mt = 0; mt < 4; mt++)
#pragma unroll
        for (int nt = 0; nt < 4; nt++)
            wmma::store_matrix_sync(
                ybase + (size_t)(wm * 64 + mt * 16) * DDIM + wn * 64 + nt * 16,
                acc[mt][nt], DDIM, wmma::mem_row_major);
}

// ---------------------------------------------------------------------------
// K6: combine  out[t] = sum_k gate_k * (ybuf[slot_k] + b2[e_k])
// ---------------------------------------------------------------------------
__global__ __launch_bounds__(128)
void combine_kernel(const float* __restrict__ b2, float4* __restrict__ out) {
    int t = blockIdx.x;
    __shared__ int   s_off[NEXP];
    __shared__ int   s_slot[TOPK];
    __shared__ int   s_e[TOPK];
    __shared__ float s_g[TOPK];
    if (threadIdx.x == 0) {
        int s = 0;
#pragma unroll
        for (int e = 0; e < NEXP; e++) {
            s_off[e] = s;
            s += ((g_count[e] + BM - 1) / BM) * BM;
        }
    }
    __syncthreads();
    if (threadIdx.x < TOPK) {
        int inv = g_inv[t * TOPK + threadIdx.x];
        int e = inv >> 14, pos = inv & (T_TOK - 1);
        s_slot[threadIdx.x] = s_off[e] + pos;
        s_e[threadIdx.x] = e;
        s_g[threadIdx.x] = g_gate[inv];
    }
    __syncthreads();
    int d4 = threadIdx.x;
    float4 acc = make_float4(0.f, 0.f, 0.f, 0.f);
#pragma unroll
    for (int k = 0; k < TOPK; k++) {
        float g = s_g[k];
        float4 y = ((const float4*)(d_ybuf + (size_t)s_slot[k] * DDIM))[d4];
        float4 bb = ((const float4*)(b2 + s_e[k] * DDIM))[d4];
        acc.x += g * (y.x + bb.x);
        acc.y += g * (y.y + bb.y);
        acc.z += g * (y.z + bb.z);
        acc.w += g * (y.w + bb.w);
    }
    out[(size_t)t * (DDIM / 4) + d4] = acc;
}

// ---------------------------------------------------------------------------
extern "C" void kernel_launch(void* const* d_in, const int* in_sizes, int n_in,
                              void* d_out, int out_size) {
    const float* x  = (const float*)d_in[0];
    const float* rw = (const float*)d_in[1];
    const float* rb = (const float*)d_in[2];
    const float* w1 = (const float*)d_in[3];
    const float* b1 = (const float*)d_in[4];
    const float* w2 = (const float*)d_in[5];
    const float* b2 = (const float*)d_in[6];
    float* out = (float*)d_out;

    cudaFuncSetAttribute(gemm1_kernel, cudaFuncAttributeMaxDynamicSharedMemorySize, DSM_BYTES);
    cudaFuncSetAttribute(gemm2_kernel, cudaFuncAttributeMaxDynamicSharedMemorySize, DSM_BYTES);

    int n4 = T_TOK * DDIM / 4;
    convx_kernel<<<(n4 + 255) / 256, 256>>>((const float4*)x, n4);
    trans_kernel<<<dim3(1024, NEXP, 2), 256>>>(w1, w2);
    router_kernel<<<T_TOK / 32, 256>>>(x, rw, rb);
    gemm1_kernel<<<dim3(HDIM / BN, T_TOK / BM, NEXP), 256, DSM_BYTES>>>(b1);
    gemm2_kernel<<<dim3(DDIM / BN, T_TOK / BM, NEXP), 256, DSM_BYTES>>>();
    combine_kernel<<<T_TOK, 128>>>(b2, (float4*)out);
}

// round 16
// speedup vs baseline: 1.1586x; 1.1586x over previous
#include <cuda_runtime.h>
#include <cuda_fp16.h>
#include <math.h>
#include <stdint.h>

#define T_TOK 16384
#define DDIM  512
#define HDIM  2048
#define NEXP  16
#define TOPK  4

#define BM    128
#define BN    128
#define BK    64
#define SA    72            // smem row stride (halves); 36 words -> conflict-free
#define SLOTS (T_TOK * TOPK + NEXP * BM)   // per-expert regions padded to BM

#define STAGE_HALVES ((BM + BN) * SA)      // 18432 halves = 36864 B
#define DSM_BYTES    (2 * STAGE_HALVES * 2)  // 73728

// ---------------------------------------------------------------------------
// device scratch (allocation-free)
// ---------------------------------------------------------------------------
__device__ int    g_count[NEXP];
__device__ int    g_tok [NEXP * T_TOK];
__device__ float  g_gate[NEXP * T_TOK];
__device__ int    g_inv [T_TOK * TOPK];                 // e*T_TOK + pos
__device__ __half d_xh  [(size_t)T_TOK * DDIM];
__device__ __half d_w1t [(size_t)NEXP * HDIM * DDIM];   // [e][n(H)][k(D)]
__device__ __half d_w2t [(size_t)NEXP * DDIM * HDIM];   // [e][n(D)][k(H)]
__device__ __half d_hbuf[(size_t)SLOTS * HDIM];         // fp16 hidden acts
__device__ float  d_ybuf[(size_t)SLOTS * DDIM];         // fp32 expert outputs

// BM-padded prefix offset of expert e
__device__ __forceinline__ int expert_off(int e) {
    int s = 0;
#pragma unroll
    for (int i = 0; i < NEXP; i++)
        if (i < e) s += ((g_count[i] + BM - 1) / BM) * BM;
    return s;
}

// ---------------------------------------------------------------------------
// helpers
// ---------------------------------------------------------------------------
__device__ __forceinline__ uint32_t smem_u32(const void* p) {
    uint32_t a;
    asm("{ .reg .u64 t; cvta.to.shared.u64 t, %1; cvt.u32.u64 %0, t; }"
        : "=r"(a) : "l"(p));
    return a;
}
#define CP_ASYNC16(dst, src, sz) \
    asm volatile("cp.async.cg.shared.global [%0], [%1], 16, %2;" \
                 :: "r"(dst), "l"(src), "r"(sz) : "memory")
#define CP_COMMIT() asm volatile("cp.async.commit_group;" ::: "memory")
#define CP_WAIT1()  asm volatile("cp.async.wait_group 1;" ::: "memory")
#define CP_WAIT0()  asm volatile("cp.async.wait_group 0;" ::: "memory")

// m16n8k16 row.col f32.f16.f16.f32 — fragment mapping validated (R3 layout;
// R3's failure was the ATS transpose bug, not this mapping)
#define MMA16816(c, a, b) asm volatile( \
    "mma.sync.aligned.m16n8k16.row.col.f32.f16.f16.f32 " \
    "{%0,%1,%2,%3}, {%4,%5,%6,%7}, {%8,%9}, {%0,%1,%2,%3};" \
    : "+f"((c)[0]), "+f"((c)[1]), "+f"((c)[2]), "+f"((c)[3]) \
    : "r"((a)[0]), "r"((a)[1]), "r"((a)[2]), "r"((a)[3]), \
      "r"((b)[0]), "r"((b)[1]))

// ---------------------------------------------------------------------------
// K1: convert x -> fp16 (+ reset expert counts)
// ---------------------------------------------------------------------------
__global__ void convx_kernel(const float4* __restrict__ x, int n4) {
    int i = blockIdx.x * blockDim.x + threadIdx.x;
    if (blockIdx.x == 0 && threadIdx.x < NEXP) g_count[threadIdx.x] = 0;
    if (i >= n4) return;
    float4 v = x[i];
    __half2 a = __floats2half2_rn(v.x, v.y);
    __half2 b = __floats2half2_rn(v.z, v.w);
    ((uint2*)d_xh)[i] = make_uint2(*(uint32_t*)&a, *(uint32_t*)&b);
}

// ---------------------------------------------------------------------------
// K2: transpose+convert BOTH weights (dst chosen in device code — ATS fix)
// ---------------------------------------------------------------------------
__global__ __launch_bounds__(256)
void trans_kernel(const float* __restrict__ w1, const float* __restrict__ w2) {
    __shared__ float t[32][33];
    int which = blockIdx.z;
    int R = which ? HDIM : DDIM;
    int C = which ? DDIM : HDIM;
    const float* srcbase = which ? w2 : w1;
    __half* dstbase = which ? d_w2t : d_w1t;
    int e = blockIdx.y;
    int rt_ = which ? (blockIdx.x & 63) : (blockIdx.x & 15);
    int ct_ = which ? (blockIdx.x >> 6) : (blockIdx.x >> 4);
    int r0 = rt_ * 32, c0 = ct_ * 32;
    const float* s = srcbase + (size_t)e * R * C;
    __half* d = dstbase + (size_t)e * R * C;
    int tx = threadIdx.x & 31, ty = threadIdx.x >> 5;
#pragma unroll
    for (int p = 0; p < 4; p++)
        t[ty + p * 8][tx] = s[(size_t)(r0 + ty + p * 8) * C + c0 + tx];
    __syncthreads();
#pragma unroll
    for (int p = 0; p < 4; p++)
        d[(size_t)(c0 + ty + p * 8) * R + r0 + tx] =
            __float2half_rn(t[tx][ty + p * 8]);
}

// ---------------------------------------------------------------------------
// K3: router (+ inverse map for combine)
// ---------------------------------------------------------------------------
__global__ __launch_bounds__(256)
void router_kernel(const float* __restrict__ x,
                   const float* __restrict__ rw,
                   const float* __restrict__ rb) {
    __shared__ float s_rw[DDIM * NEXP];
    __shared__ float s_rb[NEXP];
    for (int i = threadIdx.x; i < DDIM * NEXP; i += 256) s_rw[i] = rw[i];
    if (threadIdx.x < NEXP) s_rb[threadIdx.x] = rb[threadIdx.x];
    __syncthreads();

    int warp = threadIdx.x >> 5, lane = threadIdx.x & 31;
    int t0 = (blockIdx.x * 8 + warp) * 4;
    if (t0 >= T_TOK) return;

    float acc[4][NEXP];
#pragma unroll
    for (int tt = 0; tt < 4; tt++)
#pragma unroll
        for (int e = 0; e < NEXP; e++) acc[tt][e] = 0.f;

#pragma unroll 4
    for (int di = 0; di < 16; di++) {
        int d = di * 32 + lane;
        float xv[4];
#pragma unroll
        for (int tt = 0; tt < 4; tt++) xv[tt] = x[(size_t)(t0 + tt) * DDIM + d];
#pragma unroll
        for (int e = 0; e < NEXP; e++) {
            float w = s_rw[d * NEXP + e];
#pragma unroll
            for (int tt = 0; tt < 4; tt++) acc[tt][e] = fmaf(xv[tt], w, acc[tt][e]);
        }
    }
#pragma unroll
    for (int tt = 0; tt < 4; tt++)
#pragma unroll
        for (int e = 0; e < NEXP; e++) {
            float v = acc[tt][e];
#pragma unroll
            for (int off = 16; off > 0; off >>= 1)
                v += __shfl_xor_sync(0xffffffffu, v, off);
            acc[tt][e] = v;
        }
    if (lane == 0) {
#pragma unroll
        for (int tt = 0; tt < 4; tt++) {
            int t = t0 + tt;
            float v[NEXP];
#pragma unroll
            for (int e = 0; e < NEXP; e++) v[e] = acc[tt][e] + s_rb[e];
            float sv[TOPK]; int si[TOPK];
#pragma unroll
            for (int k = 0; k < TOPK; k++) {
                float bm = -1e30f; int bi = 0;
#pragma unroll
                for (int e = 0; e < NEXP; e++)
                    if (v[e] > bm) { bm = v[e]; bi = e; }
                sv[k] = bm; si[k] = bi; v[bi] = -1e30f;
            }
            float mx = sv[0], s = 0.f, g[TOPK];
#pragma unroll
            for (int k = 0; k < TOPK; k++) { g[k] = __expf(sv[k] - mx); s += g[k]; }
            float inv = 1.f / s;
#pragma unroll
            for (int k = 0; k < TOPK; k++) {
                int e = si[k];
                int pos = atomicAdd(&g_count[e], 1);
                g_tok [e * T_TOK + pos] = t;
                g_gate[e * T_TOK + pos] = g[k] * inv;
                g_inv [t * TOPK + k]    = e * T_TOK + pos;
            }
        }
    }
}

// ---------------------------------------------------------------------------
// hand-rolled mma mainloop stage: 4 warps (2m x 2n), warp tile 64x64
// per ks: 16 A-frag + 16 B-frag 32-bit LDS (conflict-free), 32 HMMA
// ---------------------------------------------------------------------------
__device__ __forceinline__ void mma_stage(
    const __half* As, const __half* Bs, int wm, int wn, int rq, int cq2,
    float (&acc)[4][8][4]) {
#pragma unroll
    for (int ks = 0; ks < BK / 16; ks++) {
        int kb = ks * 16;
        uint32_t a[4][4];
#pragma unroll
        for (int mt = 0; mt < 4; mt++) {
            int r = wm * 64 + mt * 16 + rq;
            a[mt][0] = *(const uint32_t*)&As[r * SA + kb + cq2];
            a[mt][1] = *(const uint32_t*)&As[(r + 8) * SA + kb + cq2];
            a[mt][2] = *(const uint32_t*)&As[r * SA + kb + cq2 + 8];
            a[mt][3] = *(const uint32_t*)&As[(r + 8) * SA + kb + cq2 + 8];
        }
#pragma unroll
        for (int nt = 0; nt < 8; nt++) {
            int n = wn * 64 + nt * 8 + rq;
            uint32_t b[2];
            b[0] = *(const uint32_t*)&Bs[n * SA + kb + cq2];
            b[1] = *(const uint32_t*)&Bs[n * SA + kb + cq2 + 8];
#pragma unroll
            for (int mt = 0; mt < 4; mt++)
                MMA16816(acc[mt][nt], a[mt], b);
        }
    }
}

// ---------------------------------------------------------------------------
// K4: GEMM1  H[slot] = relu(gather(X) @ W1^T + b1)   M=128 N=128 K=512
// register epilogue straight to hbuf (no smem C stage)
// ---------------------------------------------------------------------------
__global__ __launch_bounds__(128, 2)
void gemm1_kernel(const float* __restrict__ b1) {
    int e = blockIdx.z;
    int cnt = g_count[e];
    int m0 = blockIdx.y * BM;
    if (m0 >= cnt) return;
    int nrows = min(BM, cnt - m0);
    int n0 = blockIdx.x * BN;
    int off_e = expert_off(e);

    extern __shared__ __align__(16) char dsm[];
    __half* stage[2] = {(__half*)dsm, (__half*)dsm + STAGE_HALVES};
    __shared__ int s_tok[BM];

    int tid = threadIdx.x, wid = tid >> 5, lane = tid & 31;
    int wm = wid & 1, wn = wid >> 1;
    int rq = lane >> 2, cq2 = (lane & 3) * 2;

    if (tid < BM) s_tok[tid] = (tid < nrows) ? g_tok[e * T_TOK + m0 + tid] : -1;
    __syncthreads();

    const __half* bsrc = d_w1t + ((size_t)e * HDIM + n0) * DDIM;
    const int NC = DDIM / BK;   // 8

#define G1_LOAD(c, buf) do {                                                    \
    int kc = (c) * BK;                                                          \
    __half* As_ = stage[buf];                                                   \
    __half* Bs_ = stage[buf] + BM * SA;                                         \
    _Pragma("unroll")                                                           \
    for (int it = 0; it < 8; it++) {                                            \
        int idx = it * 128 + tid;                                               \
        int r = idx >> 3, c8 = idx & 7;                                         \
        int tok = s_tok[r];                                                     \
        const __half* src = d_xh + (size_t)(tok < 0 ? 0 : tok) * DDIM + kc + c8 * 8; \
        CP_ASYNC16(smem_u32(&As_[r * SA + c8 * 8]), src, (tok >= 0) ? 16 : 0);  \
    }                                                                           \
    _Pragma("unroll")                                                           \
    for (int it = 0; it < 8; it++) {                                            \
        int idx = it * 128 + tid;                                               \
        int r = idx >> 3, c8 = idx & 7;                                         \
        CP_ASYNC16(smem_u32(&Bs_[r * SA + c8 * 8]),                             \
                   bsrc + (size_t)r * DDIM + kc + c8 * 8, 16);                  \
    }                                                                           \
    CP_COMMIT();                                                                \
} while (0)

    float acc[4][8][4];
#pragma unroll
    for (int mt = 0; mt < 4; mt++)
#pragma unroll
        for (int nt = 0; nt < 8; nt++)
#pragma unroll
            for (int q = 0; q < 4; q++) acc[mt][nt][q] = 0.f;

    G1_LOAD(0, 0);
    G1_LOAD(1, 1);

    for (int c = 0; c < NC; c++) {
        if (c + 1 < NC) CP_WAIT1(); else CP_WAIT0();
        __syncthreads();
        int buf = c & 1;
        mma_stage(stage[buf], stage[buf] + BM * SA, wm, wn, rq, cq2, acc);
        __syncthreads();
        if (c + 2 < NC) G1_LOAD(c + 2, buf);
    }
#undef G1_LOAD

    // epilogue from registers: +b1, relu, fp16 -> hbuf
    float2 b1v[8];
#pragma unroll
    for (int nt = 0; nt < 8; nt++)
        b1v[nt] = *(const float2*)&b1[e * HDIM + n0 + wn * 64 + nt * 8 + cq2];
#pragma unroll
    for (int mt = 0; mt < 4; mt++) {
#pragma unroll
        for (int h = 0; h < 2; h++) {
            int r = wm * 64 + mt * 16 + rq + h * 8;
            if (r >= nrows) continue;
            size_t slot = (size_t)(off_e + m0 + r);
#pragma unroll
            for (int nt = 0; nt < 8; nt++) {
                int col = n0 + wn * 64 + nt * 8 + cq2;
                float v0 = acc[mt][nt][h * 2 + 0] + b1v[nt].x;
                float v1 = acc[mt][nt][h * 2 + 1] + b1v[nt].y;
                __half2 hh = __floats2half2_rn(fmaxf(v0, 0.f), fmaxf(v1, 0.f));
                *(uint32_t*)&d_hbuf[slot * HDIM + col] = *(uint32_t*)&hh;
            }
        }
    }
}

// ---------------------------------------------------------------------------
// K5: GEMM2  ybuf[slot] = H @ W2^T   M=128 N=128 K=2048
// register epilogue straight to ybuf (padded region -> unguarded store safe)
// ---------------------------------------------------------------------------
__global__ __launch_bounds__(128, 2)
void gemm2_kernel() {
    int e = blockIdx.z;
    int cnt = g_count[e];
    int m0 = blockIdx.y * BM;
    if (m0 >= cnt) return;
    int nrows = min(BM, cnt - m0);
    int n0 = blockIdx.x * BN;
    int off_e = expert_off(e);

    extern __shared__ __align__(16) char dsm[];
    __half* stage[2] = {(__half*)dsm, (__half*)dsm + STAGE_HALVES};

    int tid = threadIdx.x, wid = tid >> 5, lane = tid & 31;
    int wm = wid & 1, wn = wid >> 1;
    int rq = lane >> 2, cq2 = (lane & 3) * 2;

    const __half* asrc = d_hbuf + (size_t)(off_e + m0) * HDIM;
    const __half* bsrc = d_w2t + ((size_t)e * DDIM + n0) * HDIM;
    const int NC = HDIM / BK;   // 32

#define G2_LOAD(c, buf) do {                                                    \
    int kc = (c) * BK;                                                          \
    __half* As_ = stage[buf];                                                   \
    __half* Bs_ = stage[buf] + BM * SA;                                         \
    _Pragma("unroll")                                                           \
    for (int it = 0; it < 8; it++) {                                            \
        int idx = it * 128 + tid;                                               \
        int r = idx >> 3, c8 = idx & 7;                                         \
        int rs = (r < nrows) ? r : 0;                                           \
        CP_ASYNC16(smem_u32(&As_[r * SA + c8 * 8]),                             \
                   asrc + (size_t)rs * HDIM + kc + c8 * 8,                      \
                   (r < nrows) ? 16 : 0);                                       \
    }                                                                           \
    _Pragma("unroll")                                                           \
    for (int it = 0; it < 8; it++) {                                            \
        int idx = it * 128 + tid;                                               \
        int r = idx >> 3, c8 = idx & 7;                                         \
        CP_ASYNC16(smem_u32(&Bs_[r * SA + c8 * 8]),                             \
                   bsrc + (size_t)r * HDIM + kc + c8 * 8, 16);                  \
    }                                                                           \
    CP_COMMIT();                                                                \
} while (0)

    float acc[4][8][4];
#pragma unroll
    for (int mt = 0; mt < 4; mt++)
#pragma unroll
        for (int nt = 0; nt < 8; nt++)
#pragma unroll
            for (int q = 0; q < 4; q++) acc[mt][nt][q] = 0.f;

    G2_LOAD(0, 0);
    G2_LOAD(1, 1);

    for (int c = 0; c < NC; c++) {
        if (c + 1 < NC) CP_WAIT1(); else CP_WAIT0();
        __syncthreads();
        int buf = c & 1;
        mma_stage(stage[buf], stage[buf] + BM * SA, wm, wn, rq, cq2, acc);
        __syncthreads();
        if (c + 2 < NC) G2_LOAD(c + 2, buf);
    }
#undef G2_LOAD

    float* ybase = d_ybuf + (size_t)(off_e + m0) * DDIM + n0;
#pragma unroll
    for (int mt = 0; mt < 4; mt++)
#pragma unroll
        for (int h = 0; h < 2; h++) {
            int r = wm * 64 + mt * 16 + rq + h * 8;
#pragma unroll
            for (int nt = 0; nt < 8; nt++) {
                int col = wn * 64 + nt * 8 + cq2;
                *(float2*)&ybase[(size_t)r * DDIM + col] =
                    make_float2(acc[mt][nt][h * 2], acc[mt][nt][h * 2 + 1]);
            }
        }
}

// ---------------------------------------------------------------------------
// K6: combine  out[t] = sum_k gate_k * (ybuf[slot_k] + b2[e_k])
// ---------------------------------------------------------------------------
__global__ __launch_bounds__(128)
void combine_kernel(const float* __restrict__ b2, float4* __restrict__ out) {
    int t = blockIdx.x;
    __shared__ int   s_off[NEXP];
    __shared__ int   s_slot[TOPK];
    __shared__ int   s_e[TOPK];
    __shared__ float s_g[TOPK];
    if (threadIdx.x == 0) {
        int s = 0;
#pragma unroll
        for (int e = 0; e < NEXP; e++) {
            s_off[e] = s;
            s += ((g_count[e] + BM - 1) / BM) * BM;
        }
    }
    __syncthreads();
    if (threadIdx.x < TOPK) {
        int inv = g_inv[t * TOPK + threadIdx.x];
        int e = inv >> 14, pos = inv & (T_TOK - 1);
        s_slot[threadIdx.x] = s_off[e] + pos;
        s_e[threadIdx.x] = e;
        s_g[threadIdx.x] = g_gate[inv];
    }
    __syncthreads();
    int d4 = threadIdx.x;
    float4 acc = make_float4(0.f, 0.f, 0.f, 0.f);
#pragma unroll
    for (int k = 0; k < TOPK; k++) {
        float g = s_g[k];
        float4 y = ((const float4*)(d_ybuf + (size_t)s_slot[k] * DDIM))[d4];
        float4 bb = ((const float4*)(b2 + s_e[k] * DDIM))[d4];
        acc.x += g * (y.x + bb.x);
        acc.y += g * (y.y + bb.y);
        acc.z += g * (y.z + bb.z);
        acc.w += g * (y.w + bb.w);
    }
    out[(size_t)t * (DDIM / 4) + d4] = acc;
}

// ---------------------------------------------------------------------------
extern "C" void kernel_launch(void* const* d_in, const int* in_sizes, int n_in,
                              void* d_out, int out_size) {
    const float* x  = (const float*)d_in[0];
    const float* rw = (const float*)d_in[1];
    const float* rb = (const float*)d_in[2];
    const float* w1 = (const float*)d_in[3];
    const float* b1 = (const float*)d_in[4];
    const float* w2 = (const float*)d_in[5];
    const float* b2 = (const float*)d_in[6];
    float* out = (float*)d_out;

    cudaFuncSetAttribute(gemm1_kernel, cudaFuncAttributeMaxDynamicSharedMemorySize, DSM_BYTES);
    cudaFuncSetAttribute(gemm2_kernel, cudaFuncAttributeMaxDynamicSharedMemorySize, DSM_BYTES);

    int n4 = T_TOK * DDIM / 4;
    convx_kernel<<<(n4 + 255) / 256, 256>>>((const float4*)x, n4);
    trans_kernel<<<dim3(1024, NEXP, 2), 256>>>(w1, w2);
    router_kernel<<<T_TOK / 32, 256>>>(x, rw, rb);
    gemm1_kernel<<<dim3(HDIM / BN, T_TOK / BM, NEXP), 128, DSM_BYTES>>>(b1);
    gemm2_kernel<<<dim3(DDIM / BN, T_TOK / BM, NEXP), 128, DSM_BYTES>>>();
    combine_kernel<<<T_TOK, 128>>>(b2, (float4*)out);
}